// round 4
// baseline (speedup 1.0000x reference)
#include <cuda_runtime.h>
#include <math.h>

// ---------------------------------------------------------------------------
// PADigitalTwin, single persistent kernel.
//   Phase 1: Volterra (orders 1,3,5,7; 5 taps) -> y parked in SMEM, power partial
//   Phase 2: grid-wide reduction -> noise_std (epoch flag, all blocks co-resident)
//   Phase 3: rotate by phase noise + AWGN -> out
//
//   x           [16, 131072, 2] f32
//   coeffs_real [4, 5] f32   coeffs_imag [4, 5] f32
//   awgn        [16, 131068, 2] f32
//   phase_noise [16, 131068] f32
//   out         [16, 131068, 2] f32
// ---------------------------------------------------------------------------

#define MEMD      5
#define SLEN      131072
#define OUTLEN    131068              // SLEN - MEMD + 1
#define BATCH     16
#define JOBS_PB   (OUTLEN / 4)        // 32767 (exact), 4 outputs per job
#define JTOTAL    (JOBS_PB * BATCH)   // 524272
#define NBLK      148
#define NTHR      1024
#define JOBS_Q    (JTOTAL / NBLK)     // 3542
#define JOBS_R    (JTOTAL % NBLK)     // 56
#define MAXJOBS   (JOBS_Q + 1)        // 3543
#define SMEM_BYTES (MAXJOBS * 8 * 4)  // 113376 B: 8 floats of y per job
#define NITER     ((MAXJOBS + NTHR - 1) / NTHR)   // 4

__device__ float        g_partials[NBLK];
__device__ float        g_noise_std;
__device__ unsigned int g_done;       // zero-init; reset by last block each run
__device__ unsigned int g_ready;      // monotonically increasing epoch

__global__ __launch_bounds__(NTHR)
void pa_fused(const float* __restrict__ x,
              const float* __restrict__ crg,
              const float* __restrict__ cig,
              const float* __restrict__ awgn,
              const float* __restrict__ pn,
              float* __restrict__ out)
{
    extern __shared__ float sy[];                 // [MAXJOBS * 8]
    __shared__ float scr[20], sci[20];
    __shared__ float shr[NTHR / 32];
    __shared__ unsigned int s_e0;
    __shared__ bool s_last;

    const int tid = threadIdx.x;
    const int bid = blockIdx.x;

    // epoch snapshot BEFORE our partial deposit (increment can only happen
    // after all 148 deposits, hence after this read)
    if (tid == 0) s_e0 = *(volatile unsigned int*)&g_ready;
    if (tid < 20) {
        scr[tid] = __ldg(&crg[tid]);
        sci[tid] = __ldg(&cig[tid]);
    }
    __syncthreads();

    const int jstart = bid * JOBS_Q + (bid < JOBS_R ? bid : JOBS_R);
    const int njobs  = JOBS_Q + (bid < JOBS_R ? 1 : 0);

    // ---------------- Phase 1: Volterra -> smem, power accumulation ---------
    float acc = 0.f;
#pragma unroll
    for (int it = 0; it < NITER; it++) {
        const int l = it * NTHR + tid;            // local job index
        if (l >= njobs) break;
        const int g = jstart + l;                 // global job index
        const int b = g / JOBS_PB;
        const int j = g - b * JOBS_PB;

        const float4* xb4 = (const float4*)(x + (size_t)b * SLEN * 2);
        float I[8], Q[8], a2[8];
#pragma unroll
        for (int v = 0; v < 4; v++) {
            float4 p = __ldg(&xb4[j * 2 + v]);    // samples 4j+2v, 4j+2v+1
            I[2 * v]     = p.x;  Q[2 * v]     = p.y;
            I[2 * v + 1] = p.z;  Q[2 * v + 1] = p.w;
        }
#pragma unroll
        for (int s = 0; s < 8; s++)
            a2[s] = fmaf(I[s], I[s], Q[s] * Q[s]);

        float yr[4], yi[4];
#pragma unroll
        for (int o = 0; o < 4; o++) { yr[o] = 0.f; yi[o] = 0.f; }
#pragma unroll
        for (int m = 0; m < MEMD; m++) {
            const float cr0 = scr[m],      ci0 = sci[m];
            const float cr1 = scr[5 + m],  ci1 = sci[5 + m];
            const float cr2 = scr[10 + m], ci2 = sci[10 + m];
            const float cr3 = scr[15 + m], ci3 = sci[15 + m];
#pragma unroll
            for (int o = 0; o < 4; o++) {
                const int w = o + (MEMD - 1) - m;
                const float e = a2[w];
                const float fr = fmaf(fmaf(fmaf(cr3, e, cr2), e, cr1), e, cr0);
                const float fi = fmaf(fmaf(fmaf(ci3, e, ci2), e, ci1), e, ci0);
                yr[o] = fmaf(fr, I[w], fmaf(-fi, Q[w], yr[o]));
                yi[o] = fmaf(fr, Q[w], fmaf( fi, I[w], yi[o]));
            }
        }
#pragma unroll
        for (int o = 0; o < 4; o++)
            acc = fmaf(yr[o], yr[o], fmaf(yi[o], yi[o], acc));

        float4* s4 = (float4*)(sy + (size_t)l * 8);
        float4 t0, t1;
        t0.x = yr[0]; t0.y = yi[0]; t0.z = yr[1]; t0.w = yi[1];
        t1.x = yr[2]; t1.y = yi[2]; t1.z = yr[3]; t1.w = yi[3];
        s4[0] = t0;
        s4[1] = t1;
    }

    // block reduce (deterministic fixed tree)
#pragma unroll
    for (int off = 16; off > 0; off >>= 1)
        acc += __shfl_down_sync(0xffffffffu, acc, off);
    if ((tid & 31) == 0) shr[tid >> 5] = acc;
    __syncthreads();
    if (tid < NTHR / 32) {
        float v = shr[tid];
#pragma unroll
        for (int off = (NTHR / 32) / 2; off > 0; off >>= 1)
            v += __shfl_down_sync(0xffffffffu, v, off);
        if (tid == 0) g_partials[bid] = v;
    }

    // ---------------- Phase 2: grid-wide noise_std --------------------------
    __threadfence();
    if (tid == 0) {
        unsigned t = atomicAdd(&g_done, 1u);
        s_last = (t == (unsigned)(NBLK - 1));
    }
    __syncthreads();
    if (s_last && tid == 0) {
        double s = 0.0;
#pragma unroll
        for (int i = 0; i < NBLK; i++)
            s += (double)g_partials[i];
        double mean = s / ((double)BATCH * (double)OUTLEN);
        g_noise_std = (float)sqrt(mean * 0.5 * 1.0e-6);   // 10^(-60/10)
        g_done = 0u;                                      // reset for replay
        __threadfence();
        atomicAdd(&g_ready, 1u);                          // publish epoch
    }
    if (tid == 0) {
        const unsigned e0 = s_e0;
        while (*(volatile unsigned int*)&g_ready == e0)
            __nanosleep(64);
    }
    __syncthreads();
    __threadfence();
    const float ns = *(volatile float*)&g_noise_std;

    // ---------------- Phase 3: epilogue from smem ---------------------------
    const float KRAD = 0.008726646259971648f;             // 0.5*pi/180
#pragma unroll
    for (int it = 0; it < NITER; it++) {
        const int l = it * NTHR + tid;
        if (l >= njobs) break;
        const int g = jstart + l;
        const int b = g / JOBS_PB;
        const int j = g - b * JOBS_PB;

        const float4* s4  = (const float4*)(sy + (size_t)l * 8);
        const float4* aw4 = (const float4*)(awgn + (size_t)b * OUTLEN * 2);
        const float4* pn4 = (const float4*)(pn   + (size_t)b * OUTLEN);

        float4 s0 = s4[0];
        float4 s1 = s4[1];
        float4 p  = __ldg(&pn4[j]);
        float4 a0 = __ldg(&aw4[j * 2]);
        float4 a1 = __ldg(&aw4[j * 2 + 1]);

        float c0, sn0, c1, sn1, c2, sn2, c3, sn3;
        __sincosf(p.x * KRAD, &sn0, &c0);
        __sincosf(p.y * KRAD, &sn1, &c1);
        __sincosf(p.z * KRAD, &sn2, &c2);
        __sincosf(p.w * KRAD, &sn3, &c3);

        float4 o0, o1;
        o0.x = fmaf(a0.x, ns, s0.x * c0 - s0.y * sn0);
        o0.y = fmaf(a0.y, ns, s0.x * sn0 + s0.y * c0);
        o0.z = fmaf(a0.z, ns, s0.z * c1 - s0.w * sn1);
        o0.w = fmaf(a0.w, ns, s0.z * sn1 + s0.w * c1);
        o1.x = fmaf(a1.x, ns, s1.x * c2 - s1.y * sn2);
        o1.y = fmaf(a1.y, ns, s1.x * sn2 + s1.y * c2);
        o1.z = fmaf(a1.z, ns, s1.z * c3 - s1.w * sn3);
        o1.w = fmaf(a1.w, ns, s1.z * sn3 + s1.w * c3);

        float4* out4 = (float4*)(out + (size_t)b * OUTLEN * 2);
        out4[j * 2]     = o0;
        out4[j * 2 + 1] = o1;
    }
}

// ---------------------------------------------------------------------------
extern "C" void kernel_launch(void* const* d_in, const int* in_sizes, int n_in,
                              void* d_out, int out_size)
{
    const float* x    = (const float*)d_in[0];
    const float* cr   = (const float*)d_in[1];
    const float* ci   = (const float*)d_in[2];
    const float* awgn = (const float*)d_in[3];
    const float* pn   = (const float*)d_in[4];
    float* out        = (float*)d_out;

    static bool attr_set = false;
    if (!attr_set) {
        cudaFuncSetAttribute(pa_fused,
                             cudaFuncAttributeMaxDynamicSharedMemorySize,
                             SMEM_BYTES);
        attr_set = true;
    }

    pa_fused<<<NBLK, NTHR, SMEM_BYTES>>>(x, cr, ci, awgn, pn, out);
}

// round 5
// speedup vs baseline: 1.2554x; 1.2554x over previous
#include <cuda_runtime.h>
#include <math.h>

// ---------------------------------------------------------------------------
// PADigitalTwin: 3-launch structure.
//   pa_main  : Volterra once -> g_y (L2-resident) + per-block power partials
//   pa_reduce: 2048 partials -> noise_std
//   pa_epi   : rotate + AWGN, 2 jobs/thread, front-batched loads
//
//   x [16,131072,2]  cr/ci [4,5]  awgn [16,131068,2]  pn [16,131068]
//   out [16,131068,2]   (all f32)
// ---------------------------------------------------------------------------

#define MEMD      5
#define SLEN      131072
#define OUTLEN    131068          // SLEN - MEMD + 1
#define BATCH     16
#define TPT       4
#define JOBS_PB   (OUTLEN / TPT)  // 32767 (exact)
#define BLOCK     256
#define GRIDX     ((JOBS_PB + BLOCK - 1) / BLOCK)   // 128
#define NPART     (GRIDX * BATCH)                   // 2048

// epilogue: 2 jobs (8 complex outputs) per thread
#define ETHREADS_PB ((JOBS_PB + 1) / 2)             // 16384
#define EGRIDX      (ETHREADS_PB / BLOCK)           // 64

__device__ float g_y[(size_t)BATCH * OUTLEN * 2];   // 16.8 MB scratch
__device__ float g_partials[NPART];
__device__ float g_noise_std;

// ---------------- Pass 1: Volterra -> g_y + partials ------------------------
__global__ __launch_bounds__(BLOCK)
void pa_main(const float* __restrict__ x,
             const float* __restrict__ crg,
             const float* __restrict__ cig)
{
    // coeffs packed per-tap: scr4[m] = (cr[0][m], cr[1][m], cr[2][m], cr[3][m])
    __shared__ float4 scr4[MEMD], sci4[MEMD];
    if (threadIdx.x < MEMD) {
        const int m = threadIdx.x;
        scr4[m] = make_float4(__ldg(&crg[m]),      __ldg(&crg[5 + m]),
                              __ldg(&crg[10 + m]), __ldg(&crg[15 + m]));
    } else if (threadIdx.x < 2 * MEMD) {
        const int m = threadIdx.x - MEMD;
        sci4[m] = make_float4(__ldg(&cig[m]),      __ldg(&cig[5 + m]),
                              __ldg(&cig[10 + m]), __ldg(&cig[15 + m]));
    }
    __syncthreads();

    const int j = blockIdx.x * BLOCK + threadIdx.x;
    const int b = blockIdx.y;
    float acc = 0.f;

    if (j < JOBS_PB) {
        const float4* xb4 = (const float4*)(x + (size_t)b * SLEN * 2);
        float I[8], Q[8], a2[8];
#pragma unroll
        for (int v = 0; v < 4; v++) {
            float4 p = __ldg(&xb4[j * 2 + v]);
            I[2 * v]     = p.x;  Q[2 * v]     = p.y;
            I[2 * v + 1] = p.z;  Q[2 * v + 1] = p.w;
        }
#pragma unroll
        for (int s = 0; s < 8; s++)
            a2[s] = fmaf(I[s], I[s], Q[s] * Q[s]);

        float yr[TPT], yi[TPT];
#pragma unroll
        for (int o = 0; o < TPT; o++) { yr[o] = 0.f; yi[o] = 0.f; }

#pragma unroll
        for (int m = 0; m < MEMD; m++) {
            const float4 cm = scr4[m];     // one LDS.128, warp-broadcast
            const float4 dm = sci4[m];
#pragma unroll
            for (int o = 0; o < TPT; o++) {
                const int w = o + (MEMD - 1) - m;
                const float e = a2[w];
                const float fr = fmaf(fmaf(fmaf(cm.w, e, cm.z), e, cm.y), e, cm.x);
                const float fi = fmaf(fmaf(fmaf(dm.w, e, dm.z), e, dm.y), e, dm.x);
                yr[o] = fmaf(fr, I[w], fmaf(-fi, Q[w], yr[o]));
                yi[o] = fmaf(fr, Q[w], fmaf( fi, I[w], yi[o]));
            }
        }

#pragma unroll
        for (int o = 0; o < TPT; o++)
            acc = fmaf(yr[o], yr[o], fmaf(yi[o], yi[o], acc));

        float4* y4 = (float4*)(g_y + (size_t)b * OUTLEN * 2);
        float4 s0, s1;
        s0.x = yr[0]; s0.y = yi[0]; s0.z = yr[1]; s0.w = yi[1];
        s1.x = yr[2]; s1.y = yi[2]; s1.z = yr[3]; s1.w = yi[3];
        y4[j * 2]     = s0;
        y4[j * 2 + 1] = s1;
    }

    __shared__ float shr[BLOCK / 32];
#pragma unroll
    for (int off = 16; off > 0; off >>= 1)
        acc += __shfl_down_sync(0xffffffffu, acc, off);
    if ((threadIdx.x & 31) == 0) shr[threadIdx.x >> 5] = acc;
    __syncthreads();
    if (threadIdx.x < BLOCK / 32) {
        float v = shr[threadIdx.x];
#pragma unroll
        for (int off = (BLOCK / 32) / 2; off > 0; off >>= 1)
            v += __shfl_down_sync(0xffu, v, off);
        if (threadIdx.x == 0)
            g_partials[blockIdx.y * GRIDX + blockIdx.x] = v;
    }
}

// ---------------- Pass 2: noise_std ----------------------------------------
__global__ __launch_bounds__(256)
void pa_reduce()
{
    __shared__ double sh[256];
    double s = 0.0;
#pragma unroll
    for (int i = 0; i < NPART / 256; i++)
        s += (double)g_partials[threadIdx.x + i * 256];
    sh[threadIdx.x] = s;
    __syncthreads();
#pragma unroll
    for (int off = 128; off > 0; off >>= 1) {
        if (threadIdx.x < off) sh[threadIdx.x] += sh[threadIdx.x + off];
        __syncthreads();
    }
    if (threadIdx.x == 0) {
        double mean = sh[0] / ((double)BATCH * (double)OUTLEN);
        g_noise_std = (float)sqrt(mean * 0.5 * 1.0e-6);   // 10^(-60/10)
    }
}

// ---------------- Pass 3: epilogue, 2 jobs / thread -------------------------
__global__ __launch_bounds__(BLOCK)
void pa_epi(const float* __restrict__ awgn,
            const float* __restrict__ pn,
            float* __restrict__ out)
{
    const int t = blockIdx.x * BLOCK + threadIdx.x;     // 0..16383
    const int b = blockIdx.y;
    const int j0 = 2 * t;
    const bool has2 = (j0 + 1) < JOBS_PB;               // last thread: 1 job

    const float4* y4  = (const float4*)(g_y  + (size_t)b * OUTLEN * 2);
    const float4* aw4 = (const float4*)(awgn + (size_t)b * OUTLEN * 2);
    const float4* pn4 = (const float4*)(pn   + (size_t)b * OUTLEN);

    // front-batched loads (MLP ~10)
    float4 y0 = y4[j0 * 2];
    float4 y1 = y4[j0 * 2 + 1];
    float4 p0 = __ldg(&pn4[j0]);
    float4 a0 = __ldg(&aw4[j0 * 2]);
    float4 a1 = __ldg(&aw4[j0 * 2 + 1]);
    float4 y2, y3, p1, a2, a3;
    const int j1 = has2 ? (j0 + 1) : j0;
    y2 = y4[j1 * 2];
    y3 = y4[j1 * 2 + 1];
    p1 = __ldg(&pn4[j1]);
    a2 = __ldg(&aw4[j1 * 2]);
    a3 = __ldg(&aw4[j1 * 2 + 1]);

    const float ns = g_noise_std;
    const float KRAD = 0.008726646259971648f;           // 0.5*pi/180

    float4* out4 = (float4*)(out + (size_t)b * OUTLEN * 2);

    {
        float c0, s0, c1, s1, c2, s2, c3, s3;
        __sincosf(p0.x * KRAD, &s0, &c0);
        __sincosf(p0.y * KRAD, &s1, &c1);
        __sincosf(p0.z * KRAD, &s2, &c2);
        __sincosf(p0.w * KRAD, &s3, &c3);
        float4 o0, o1;
        o0.x = fmaf(a0.x, ns, y0.x * c0 - y0.y * s0);
        o0.y = fmaf(a0.y, ns, y0.x * s0 + y0.y * c0);
        o0.z = fmaf(a0.z, ns, y0.z * c1 - y0.w * s1);
        o0.w = fmaf(a0.w, ns, y0.z * s1 + y0.w * c1);
        o1.x = fmaf(a1.x, ns, y1.x * c2 - y1.y * s2);
        o1.y = fmaf(a1.y, ns, y1.x * s2 + y1.y * c2);
        o1.z = fmaf(a1.z, ns, y1.z * c3 - y1.w * s3);
        o1.w = fmaf(a1.w, ns, y1.z * s3 + y1.w * c3);
        out4[j0 * 2]     = o0;
        out4[j0 * 2 + 1] = o1;
    }
    if (has2) {
        float c0, s0, c1, s1, c2, s2, c3, s3;
        __sincosf(p1.x * KRAD, &s0, &c0);
        __sincosf(p1.y * KRAD, &s1, &c1);
        __sincosf(p1.z * KRAD, &s2, &c2);
        __sincosf(p1.w * KRAD, &s3, &c3);
        float4 o0, o1;
        o0.x = fmaf(a2.x, ns, y2.x * c0 - y2.y * s0);
        o0.y = fmaf(a2.y, ns, y2.x * s0 + y2.y * c0);
        o0.z = fmaf(a2.z, ns, y2.z * c1 - y2.w * s1);
        o0.w = fmaf(a2.w, ns, y2.z * s1 + y2.w * c1);
        o1.x = fmaf(a3.x, ns, y3.x * c2 - y3.y * s2);
        o1.y = fmaf(a3.y, ns, y3.x * s2 + y3.y * c2);
        o1.z = fmaf(a3.z, ns, y3.z * c3 - y3.w * s3);
        o1.w = fmaf(a3.w, ns, y3.z * s3 + y3.w * c3);
        out4[j1 * 2]     = o0;
        out4[j1 * 2 + 1] = o1;
    }
}

// ---------------------------------------------------------------------------
extern "C" void kernel_launch(void* const* d_in, const int* in_sizes, int n_in,
                              void* d_out, int out_size)
{
    const float* x    = (const float*)d_in[0];
    const float* cr   = (const float*)d_in[1];
    const float* ci   = (const float*)d_in[2];
    const float* awgn = (const float*)d_in[3];
    const float* pn   = (const float*)d_in[4];
    float* out        = (float*)d_out;

    pa_main<<<dim3(GRIDX, BATCH), BLOCK>>>(x, cr, ci);
    pa_reduce<<<1, 256>>>();
    pa_epi<<<dim3(EGRIDX, BATCH), BLOCK>>>(awgn, pn, out);
}